// round 2
// baseline (speedup 1.0000x reference)
#include <cuda_runtime.h>

#define NN 100000
#define EE 1600000

// ---------------- scratch (static device globals; no allocation) ----------------
__device__ int   g_is64;
__device__ int   g_src[EE];
__device__ int   g_dstE[EE];
__device__ int   g_deg[NN];
__device__ int   g_rowptr[NN + 1];
__device__ int   g_cursor[NN];
__device__ int   g_bsum[128];
__device__ int   g_bexc[128];
__device__ int   g_col[EE + NN];
__device__ int   g_edst[EE + NN];
__device__ float g_h[NN * 64];
__device__ float g_act[NN * 64];
__device__ float g_adst[NN * 8];
__device__ float g_asrc[NN * 8];
__device__ float g_w[(EE + NN) * 8];

// ---------------- init: deg=1 (self-loop) + dtype detect ----------------
__global__ void k_init(const void* ei) {
    int i = blockIdx.x * blockDim.x + threadIdx.x;
    if (i < NN) g_deg[i] = 1;
    if (i == 0) {
        const long long* p = (const long long*)ei;
        int ok = 1;
        for (int k = 0; k < 8; k++) {
            long long v = p[k];
            if (v < 0 || v >= NN) ok = 0;
        }
        g_is64 = ok;
    }
}

// ---------------- convert + histogram fused ----------------
__global__ void k_convhist(const void* ei) {
    int e = blockIdx.x * blockDim.x + threadIdx.x;
    if (e >= EE) return;
    int s, d;
    if (g_is64) {
        const long long* p = (const long long*)ei;
        s = (int)p[e];
        d = (int)p[EE + e];
    } else {
        const int* p = (const int*)ei;
        s = p[e];
        d = p[EE + e];
    }
    g_src[e] = s;
    g_dstE[e] = d;
    if (s != d) atomicAdd(&g_deg[d], 1);  // original self-loops dropped (masked to -inf -> exp 0)
}

// ---------------- scan ----------------
__global__ void k_scan1() {
    __shared__ int sh[1024];
    int tid = threadIdx.x;
    int i = blockIdx.x * 1024 + tid;
    int v = (i < NN) ? g_deg[i] : 0;
    sh[tid] = v;
    __syncthreads();
    for (int o = 1; o < 1024; o <<= 1) {
        int t = (tid >= o) ? sh[tid - o] : 0;
        __syncthreads();
        sh[tid] += t;
        __syncthreads();
    }
    if (i < NN) g_rowptr[i] = sh[tid] - v;
    if (tid == 1023) g_bsum[blockIdx.x] = sh[1023];
}

__global__ void k_scan2(int nb) {
    __shared__ int sh[128];
    int tid = threadIdx.x;
    int v = (tid < nb) ? g_bsum[tid] : 0;
    sh[tid] = v;
    __syncthreads();
    for (int o = 1; o < 128; o <<= 1) {
        int t = (tid >= o) ? sh[tid - o] : 0;
        __syncthreads();
        sh[tid] += t;
        __syncthreads();
    }
    if (tid < nb) g_bexc[tid] = sh[tid] - v;
    if (tid == nb - 1) g_rowptr[NN] = sh[tid];
}

__global__ void k_scan3() {
    int i = blockIdx.x * blockDim.x + threadIdx.x;
    if (i < NN) {
        int r = g_rowptr[i] + g_bexc[i >> 10];
        g_rowptr[i] = r;
        g_cursor[i] = r;
    }
}

// ---------------- scatter: build col + edge-dst ----------------
__global__ void k_scatter() {
    int e = blockIdx.x * blockDim.x + threadIdx.x;
    if (e >= EE + NN) return;
    if (e < EE) {
        int s = g_src[e], d = g_dstE[e];
        if (s != d) {
            int p = atomicAdd(&g_cursor[d], 1);
            g_col[p] = s;
            g_edst[p] = d;
        }
    } else {
        int n = e - EE;
        int p = atomicAdd(&g_cursor[n], 1);
        g_col[p] = n;
        g_edst[p] = n;
    }
}

// ---------------- tiled FFMA GEMM: C[N,NOUT] = A[N,K] @ W[K,NOUT] ----------------
// 8 rows x 4 cols per thread; As stored k-major [kk][row] for LDS.128 fragment loads.
template <int K, int NOUT>
__global__ __launch_bounds__(256) void k_gemm(const float* __restrict__ A,
                                              const float* __restrict__ W,
                                              int use_g_act) {
    constexpr int TX = NOUT / 4;
    constexpr int TY = 256 / TX;
    constexpr int MROWS = TY * 8;
    __shared__ float As[32][MROWS + 4];
    __shared__ float Ws[32 * NOUT];
    const float* Ap = use_g_act ? (const float*)g_act : A;

    int tid = threadIdx.x;
    int row0 = blockIdx.x * MROWS;
    int tx = tid % TX, ty = tid / TX;
    int r0 = ty * 8, c0 = tx * 4;

    float acc[8][4];
#pragma unroll
    for (int i = 0; i < 8; i++)
#pragma unroll
        for (int j = 0; j < 4; j++) acc[i][j] = 0.f;

    for (int kb = 0; kb < K; kb += 32) {
        __syncthreads();
        // W tile: rows kb..kb+31 contiguous
        for (int i = tid; i < 32 * NOUT / 4; i += 256)
            ((float4*)Ws)[i] = ((const float4*)&W[kb * NOUT])[i];
        // A tile: transpose into k-major
        for (int f = tid; f < MROWS * 8; f += 256) {
            int r = f >> 3, c4 = f & 7;
            float4 v = make_float4(0.f, 0.f, 0.f, 0.f);
            if (row0 + r < NN)
                v = *(const float4*)&Ap[(row0 + r) * K + kb + c4 * 4];
            As[c4 * 4 + 0][r] = v.x;
            As[c4 * 4 + 1][r] = v.y;
            As[c4 * 4 + 2][r] = v.z;
            As[c4 * 4 + 3][r] = v.w;
        }
        __syncthreads();
#pragma unroll
        for (int kk = 0; kk < 32; kk++) {
            float4 b = *(float4*)&Ws[kk * NOUT + c0];
            float4 a0 = *(float4*)&As[kk][r0];
            float4 a1 = *(float4*)&As[kk][r0 + 4];
            float av[8] = {a0.x, a0.y, a0.z, a0.w, a1.x, a1.y, a1.z, a1.w};
#pragma unroll
            for (int i = 0; i < 8; i++) {
                acc[i][0] += av[i] * b.x;
                acc[i][1] += av[i] * b.y;
                acc[i][2] += av[i] * b.z;
                acc[i][3] += av[i] * b.w;
            }
        }
    }
#pragma unroll
    for (int i = 0; i < 8; i++) {
        int r = row0 + r0 + i;
        if (r < NN)
            *(float4*)&g_h[r * NOUT + c0] =
                make_float4(acc[i][0], acc[i][1], acc[i][2], acc[i][3]);
    }
}

// ---------------- per-node attention dots ----------------
__global__ __launch_bounds__(256) void k_att8(const float* __restrict__ att) {
    int t = blockIdx.x * blockDim.x + threadIdx.x;
    int n = t >> 5, lane = t & 31;
    if (n >= NN) return;
    float v0 = g_h[n * 64 + lane];
    float v1 = g_h[n * 64 + 32 + lane];
    int hh = lane >> 3, c = lane & 7;
    float d0 = v0 * att[hh * 16 + c];
    float d1 = v1 * att[(hh + 4) * 16 + c];
    float s0 = v0 * att[hh * 16 + 8 + c];
    float s1 = v1 * att[(hh + 4) * 16 + 8 + c];
    for (int o = 1; o < 8; o <<= 1) {
        d0 += __shfl_xor_sync(0xffffffffu, d0, o);
        d1 += __shfl_xor_sync(0xffffffffu, d1, o);
        s0 += __shfl_xor_sync(0xffffffffu, s0, o);
        s1 += __shfl_xor_sync(0xffffffffu, s1, o);
    }
    if (c == 0) {
        g_adst[n * 8 + hh] = d0;
        g_adst[n * 8 + hh + 4] = d1;
        g_asrc[n * 8 + hh] = s0;
        g_asrc[n * 8 + hh + 4] = s1;
    }
}

__global__ __launch_bounds__(256) void k_att32(const float* __restrict__ att) {
    int t = blockIdx.x * blockDim.x + threadIdx.x;
    int n = t >> 5, lane = t & 31;
    if (n >= NN) return;
    float v = g_h[n * 32 + lane];
    float d = v * att[lane];
    float s = v * att[32 + lane];
    for (int o = 1; o < 32; o <<= 1) {
        d += __shfl_xor_sync(0xffffffffu, d, o);
        s += __shfl_xor_sync(0xffffffffu, s, o);
    }
    if (lane == 0) {
        g_adst[n] = d;
        g_asrc[n] = s;
    }
}

// ---------------- edge-parallel softmax weights (CSR order) ----------------
// H=8: one thread per (edge, head)
__global__ __launch_bounds__(256) void k_w8() {
    int t = blockIdx.x * blockDim.x + threadIdx.x;
    int cnt = g_rowptr[NN];
    int e = t >> 3;
    if (e >= cnt) return;
    int h = t & 7;
    int s = g_col[e], d = g_edst[e];
    float a = g_adst[d * 8 + h] + g_asrc[s * 8 + h];
    a = a > 0.f ? a : 0.2f * a;
    g_w[e * 8 + h] = __expf(a);
}

// H=1: one thread per edge
__global__ __launch_bounds__(256) void k_w1() {
    int e = blockIdx.x * blockDim.x + threadIdx.x;
    int cnt = g_rowptr[NN];
    if (e >= cnt) return;
    int s = g_col[e], d = g_edst[e];
    float a = g_adst[d] + g_asrc[s];
    a = a > 0.f ? a : 0.2f * a;
    g_w[e] = __expf(a);
}

// ---------------- aggregate: one warp per dst node, no shuffles ----------------
__global__ __launch_bounds__(256) void k_agg8(const float* __restrict__ bias, int do_elu) {
    int t = blockIdx.x * blockDim.x + threadIdx.x;
    int n = t >> 5, lane = t & 31;
    if (n >= NN) return;
    int start = g_rowptr[n], end = g_rowptr[n + 1];
    int hh = lane >> 3;

    float acc0 = 0.f, acc1 = 0.f, d0 = 0.f, d1 = 0.f;
    for (int e = start; e < end; e++) {
        int s = g_col[e];                  // uniform broadcast
        float w = g_w[e * 8 + hh];         // head for cols 0..31
        float w2 = g_w[e * 8 + 4 + hh];    // head for cols 32..63
        acc0 += g_h[s * 64 + lane] * w;
        acc1 += g_h[s * 64 + 32 + lane] * w2;
        d0 += w;
        d1 += w2;
    }
    float o0 = acc0 / d0 + bias[lane];
    float o1 = acc1 / d1 + bias[lane + 32];
    if (do_elu) {
        o0 = o0 > 0.f ? o0 : expm1f(o0);
        o1 = o1 > 0.f ? o1 : expm1f(o1);
    }
    g_act[n * 64 + lane] = o0;
    g_act[n * 64 + 32 + lane] = o1;
}

__global__ __launch_bounds__(256) void k_agg32(const float* __restrict__ bias,
                                               float* __restrict__ outp) {
    int t = blockIdx.x * blockDim.x + threadIdx.x;
    int n = t >> 5, lane = t & 31;
    if (n >= NN) return;
    int start = g_rowptr[n], end = g_rowptr[n + 1];

    float acc = 0.f, dacc = 0.f;
    for (int e = start; e < end; e++) {
        int s = g_col[e];
        float w = g_w[e];
        acc += g_h[s * 32 + lane] * w;
        dacc += w;
    }
    outp[n * 32 + lane] = acc / dacc + bias[lane];
}

// ---------------- launch ----------------
extern "C" void kernel_launch(void* const* d_in, const int* in_sizes, int n_in,
                              void* d_out, int out_size) {
    const float* x    = (const float*)d_in[0];
    const void*  ei   = d_in[1];
    const float* W1   = (const float*)d_in[2];
    const float* att1 = (const float*)d_in[3];
    const float* b1   = (const float*)d_in[4];
    const float* W2   = (const float*)d_in[5];
    const float* att2 = (const float*)d_in[6];
    const float* b2   = (const float*)d_in[7];
    const float* W3   = (const float*)d_in[8];
    const float* att3 = (const float*)d_in[9];
    const float* b3   = (const float*)d_in[10];
    float* out = (float*)d_out;

    const int TB = 256;
    const int warpGrid = (NN * 32 + TB - 1) / TB;
    const int wGrid8 = ((EE + NN) * 8 + TB - 1) / TB;
    const int wGrid1 = ((EE + NN) + TB - 1) / TB;

    // CSR build (dst layer-invariant)
    k_init<<<(NN + TB - 1) / TB, TB>>>(ei);
    k_convhist<<<(EE + TB - 1) / TB, TB>>>(ei);
    int nb = (NN + 1023) / 1024;
    k_scan1<<<nb, 1024>>>();
    k_scan2<<<1, 128>>>(nb);
    k_scan3<<<(NN + TB - 1) / TB, TB>>>();
    k_scatter<<<(EE + NN + TB - 1) / TB, TB>>>();

    // Layer 1: 128 -> 8x8
    k_gemm<128, 64><<<(NN + 127) / 128, TB>>>(x, W1, 0);
    k_att8<<<warpGrid, TB>>>(att1);
    k_w8<<<wGrid8, TB>>>();
    k_agg8<<<warpGrid, TB>>>(b1, 1);

    // Layer 2: 64 -> 8x8
    k_gemm<64, 64><<<(NN + 127) / 128, TB>>>(nullptr, W2, 1);
    k_att8<<<warpGrid, TB>>>(att2);
    k_w8<<<wGrid8, TB>>>();
    k_agg8<<<warpGrid, TB>>>(b2, 1);

    // Layer 3: 64 -> 1x32
    k_gemm<64, 32><<<(NN + 255) / 256, TB>>>(nullptr, W3, 1);
    k_att32<<<warpGrid, TB>>>(att3);
    k_w1<<<wGrid1, TB>>>();
    k_agg32<<<warpGrid, TB>>>(b3, out);
}

// round 3
// speedup vs baseline: 1.2908x; 1.2908x over previous
#include <cuda_runtime.h>

#define NN 100000
#define EE 1600000

// ---------------- scratch (static device globals; no allocation) ----------------
__device__ int   g_is64;
__device__ int   g_src[EE];
__device__ int   g_dstE[EE];
__device__ int   g_deg[NN];
__device__ int   g_rowptr[NN + 1];
__device__ int   g_cursor[NN];
__device__ int   g_bsum[128];
__device__ int   g_bexc[128];
__device__ int   g_col[EE + NN];
__device__ float g_h[NN * 64];
__device__ float g_act[NN * 64];
__device__ float g_adst[NN * 8];
__device__ float g_asrc[NN * 8];

// ---------------- init: deg=1 (self-loop) + dtype detect ----------------
__global__ void k_init(const void* ei) {
    int i = blockIdx.x * blockDim.x + threadIdx.x;
    if (i < NN) g_deg[i] = 1;
    if (i == 0) {
        const long long* p = (const long long*)ei;
        int ok = 1;
        for (int k = 0; k < 8; k++) {
            long long v = p[k];
            if (v < 0 || v >= NN) ok = 0;
        }
        g_is64 = ok;
    }
}

// ---------------- convert + histogram fused ----------------
__global__ void k_convhist(const void* ei) {
    int e = blockIdx.x * blockDim.x + threadIdx.x;
    if (e >= EE) return;
    int s, d;
    if (g_is64) {
        const long long* p = (const long long*)ei;
        s = (int)p[e];
        d = (int)p[EE + e];
    } else {
        const int* p = (const int*)ei;
        s = p[e];
        d = p[EE + e];
    }
    g_src[e] = s;
    g_dstE[e] = d;
    if (s != d) atomicAdd(&g_deg[d], 1);  // original self-loops dropped (exp(-1e9-amax)==0)
}

// ---------------- scan ----------------
__global__ void k_scan1() {
    __shared__ int sh[1024];
    int tid = threadIdx.x;
    int i = blockIdx.x * 1024 + tid;
    int v = (i < NN) ? g_deg[i] : 0;
    sh[tid] = v;
    __syncthreads();
    for (int o = 1; o < 1024; o <<= 1) {
        int t = (tid >= o) ? sh[tid - o] : 0;
        __syncthreads();
        sh[tid] += t;
        __syncthreads();
    }
    if (i < NN) g_rowptr[i] = sh[tid] - v;
    if (tid == 1023) g_bsum[blockIdx.x] = sh[1023];
}

__global__ void k_scan2(int nb) {
    __shared__ int sh[128];
    int tid = threadIdx.x;
    int v = (tid < nb) ? g_bsum[tid] : 0;
    sh[tid] = v;
    __syncthreads();
    for (int o = 1; o < 128; o <<= 1) {
        int t = (tid >= o) ? sh[tid - o] : 0;
        __syncthreads();
        sh[tid] += t;
        __syncthreads();
    }
    if (tid < nb) g_bexc[tid] = sh[tid] - v;
    if (tid == nb - 1) g_rowptr[NN] = sh[tid];
}

__global__ void k_scan3() {
    int i = blockIdx.x * blockDim.x + threadIdx.x;
    if (i < NN) {
        int r = g_rowptr[i] + g_bexc[i >> 10];
        g_rowptr[i] = r;
        g_cursor[i] = r;
    }
}

__global__ void k_scatter() {
    int e = blockIdx.x * blockDim.x + threadIdx.x;
    if (e >= EE + NN) return;
    if (e < EE) {
        int s = g_src[e], d = g_dstE[e];
        if (s != d) {
            int p = atomicAdd(&g_cursor[d], 1);
            g_col[p] = s;
        }
    } else {
        int n = e - EE;
        int p = atomicAdd(&g_cursor[n], 1);
        g_col[p] = n;
    }
}

// ---------------- tiled FFMA GEMM (R1 version, known-good) ----------------
template <int K, int NOUT, int MROWS, int TX>
__global__ __launch_bounds__(256) void k_gemm(const float* __restrict__ A,
                                              const float* __restrict__ W,
                                              int use_g_act) {
    __shared__ float Ws[K * NOUT];
    __shared__ float As[MROWS][36];
    const float* Ap = use_g_act ? (const float*)g_act : A;

    int tid = threadIdx.x;
    int row0 = blockIdx.x * MROWS;

    for (int i = tid; i < K * NOUT / 4; i += 256)
        ((float4*)Ws)[i] = ((const float4*)W)[i];

    int tx = tid % TX, ty = tid / TX;
    int r0 = ty * 4, c0 = tx * 4;
    float acc[4][4];
#pragma unroll
    for (int i = 0; i < 4; i++)
#pragma unroll
        for (int j = 0; j < 4; j++) acc[i][j] = 0.f;

    for (int kb = 0; kb < K; kb += 32) {
        __syncthreads();
        for (int f = tid; f < MROWS * 8; f += 256) {
            int r = f >> 3, c4 = f & 7;
            float4 v = make_float4(0.f, 0.f, 0.f, 0.f);
            if (row0 + r < NN)
                v = *(const float4*)&Ap[(row0 + r) * K + kb + c4 * 4];
            *(float4*)&As[r][c4 * 4] = v;
        }
        __syncthreads();
#pragma unroll
        for (int kk = 0; kk < 32; kk++) {
            float a0 = As[r0 + 0][kk];
            float a1 = As[r0 + 1][kk];
            float a2 = As[r0 + 2][kk];
            float a3 = As[r0 + 3][kk];
            float4 b = *(float4*)&Ws[(kb + kk) * NOUT + c0];
            acc[0][0] += a0 * b.x; acc[0][1] += a0 * b.y; acc[0][2] += a0 * b.z; acc[0][3] += a0 * b.w;
            acc[1][0] += a1 * b.x; acc[1][1] += a1 * b.y; acc[1][2] += a1 * b.z; acc[1][3] += a1 * b.w;
            acc[2][0] += a2 * b.x; acc[2][1] += a2 * b.y; acc[2][2] += a2 * b.z; acc[2][3] += a2 * b.w;
            acc[3][0] += a3 * b.x; acc[3][1] += a3 * b.y; acc[3][2] += a3 * b.z; acc[3][3] += a3 * b.w;
        }
    }
#pragma unroll
    for (int i = 0; i < 4; i++) {
        int r = row0 + r0 + i;
        if (r < NN)
            *(float4*)&g_h[r * NOUT + c0] =
                make_float4(acc[i][0], acc[i][1], acc[i][2], acc[i][3]);
    }
}

// ---------------- per-node attention dots ----------------
__global__ __launch_bounds__(256) void k_att8(const float* __restrict__ att) {
    int t = blockIdx.x * blockDim.x + threadIdx.x;
    int n = t >> 5, lane = t & 31;
    if (n >= NN) return;
    float v0 = g_h[n * 64 + lane];
    float v1 = g_h[n * 64 + 32 + lane];
    int hh = lane >> 3, c = lane & 7;
    float d0 = v0 * att[hh * 16 + c];
    float d1 = v1 * att[(hh + 4) * 16 + c];
    float s0 = v0 * att[hh * 16 + 8 + c];
    float s1 = v1 * att[(hh + 4) * 16 + 8 + c];
    for (int o = 1; o < 8; o <<= 1) {
        d0 += __shfl_xor_sync(0xffffffffu, d0, o);
        d1 += __shfl_xor_sync(0xffffffffu, d1, o);
        s0 += __shfl_xor_sync(0xffffffffu, s0, o);
        s1 += __shfl_xor_sync(0xffffffffu, s1, o);
    }
    if (c == 0) {
        g_adst[n * 8 + hh] = d0;
        g_adst[n * 8 + hh + 4] = d1;
        g_asrc[n * 8 + hh] = s0;
        g_asrc[n * 8 + hh + 4] = s1;
    }
}

__global__ __launch_bounds__(256) void k_att32(const float* __restrict__ att) {
    int t = blockIdx.x * blockDim.x + threadIdx.x;
    int n = t >> 5, lane = t & 31;
    if (n >= NN) return;
    float v = g_h[n * 32 + lane];
    float d = v * att[lane];
    float s = v * att[32 + lane];
    for (int o = 1; o < 32; o <<= 1) {
        d += __shfl_xor_sync(0xffffffffu, d, o);
        s += __shfl_xor_sync(0xffffffffu, s, o);
    }
    if (lane == 0) {
        g_adst[n] = d;
        g_asrc[n] = s;
    }
}

// ---------------- aggregate H=8: warp per node, smem-staged weights ----------------
// Phase A: lanes = (edge 0..3) x (head 0..7), compute 32 exps in parallel.
// Phase B: per edge, weights via LDS broadcast; each lane gathers 2 cols (LDG.64).
__global__ __launch_bounds__(256) void k_agg8(const float* __restrict__ bias, int do_elu) {
    __shared__ float sw[8][32];
    int t = blockIdx.x * blockDim.x + threadIdx.x;
    int n = t >> 5, lane = t & 31;
    if (n >= NN) return;
    const unsigned full = 0xffffffffu;
    int wb = (threadIdx.x >> 5);
    int start = g_rowptr[n], end = g_rowptr[n + 1];
    int hc = lane & 7;       // head for phase A
    int hB = lane >> 2;      // head for phase B (cols 2*lane, 2*lane+1)

    float adst_h = g_adst[n * 8 + hc];
    float2 acc = make_float2(0.f, 0.f);
    float dsum = 0.f;

    for (int base = start; base < end; base += 4) {
        int e = base + (lane >> 3);
        float ex = 0.f;
        int scol = 0;
        if (e < end) {
            scol = g_col[e];
            float a = adst_h + g_asrc[scol * 8 + hc];
            a = a > 0.f ? a : 0.2f * a;
            ex = __expf(a);
        }
        sw[wb][lane] = ex;
        __syncwarp();
#pragma unroll
        for (int j = 0; j < 4; j++) {
            if (base + j >= end) break;
            int s = __shfl_sync(full, scol, j * 8);
            float w = sw[wb][j * 8 + hB];
            float2 hv = *(const float2*)&g_h[s * 64 + lane * 2];
            acc.x += hv.x * w;
            acc.y += hv.y * w;
            dsum += w;
        }
        __syncwarp();
    }
    float inv = 1.f / dsum;
    float o0 = acc.x * inv + bias[lane * 2];
    float o1 = acc.y * inv + bias[lane * 2 + 1];
    if (do_elu) {
        o0 = o0 > 0.f ? o0 : expm1f(o0);
        o1 = o1 > 0.f ? o1 : expm1f(o1);
    }
    *(float2*)&g_act[n * 64 + lane * 2] = make_float2(o0, o1);
}

// ---------------- aggregate H=1: warp per node, paired-edge float2 gather ----------------
__global__ __launch_bounds__(256) void k_agg32(const float* __restrict__ bias,
                                               float* __restrict__ outp) {
    int t = blockIdx.x * blockDim.x + threadIdx.x;
    int n = t >> 5, lane = t & 31;
    if (n >= NN) return;
    const unsigned full = 0xffffffffu;
    int start = g_rowptr[n], end = g_rowptr[n + 1];
    int half = lane >> 4;       // 0: even edges, 1: odd edges
    int c2 = (lane & 15) * 2;   // 2 cols per lane

    float adst = g_adst[n];
    float2 acc = make_float2(0.f, 0.f);
    float dsum = 0.f;

    for (int base = start; base < end; base += 32) {
        // Phase A: 32 exps in parallel (one edge per lane)
        int e = base + lane;
        float ex = 0.f;
        int scol = 0;
        if (e < end) {
            scol = g_col[e];
            float a = adst + g_asrc[scol];
            a = a > 0.f ? a : 0.2f * a;
            ex = __expf(a);
        }
        // Phase B: two edges per iteration (16 lanes each)
        int cnt = min(32, end - base);
#pragma unroll 4
        for (int j2 = 0; j2 * 2 < cnt; j2++) {
            int j = j2 * 2 + half;
            int s = __shfl_sync(full, scol, j);
            float w = __shfl_sync(full, ex, j);
            if (j < cnt) {
                float2 hv = *(const float2*)&g_h[s * 32 + c2];
                acc.x += hv.x * w;
                acc.y += hv.y * w;
                dsum += w;
            }
        }
    }
    // combine the two edge-halves
    acc.x += __shfl_xor_sync(full, acc.x, 16);
    acc.y += __shfl_xor_sync(full, acc.y, 16);
    dsum += __shfl_xor_sync(full, dsum, 16);
    if (lane < 16) {
        float inv = 1.f / dsum;
        outp[n * 32 + c2] = acc.x * inv + bias[c2];
        outp[n * 32 + c2 + 1] = acc.y * inv + bias[c2 + 1];
    }
}

// ---------------- launch ----------------
extern "C" void kernel_launch(void* const* d_in, const int* in_sizes, int n_in,
                              void* d_out, int out_size) {
    const float* x    = (const float*)d_in[0];
    const void*  ei   = d_in[1];
    const float* W1   = (const float*)d_in[2];
    const float* att1 = (const float*)d_in[3];
    const float* b1   = (const float*)d_in[4];
    const float* W2   = (const float*)d_in[5];
    const float* att2 = (const float*)d_in[6];
    const float* b2   = (const float*)d_in[7];
    const float* W3   = (const float*)d_in[8];
    const float* att3 = (const float*)d_in[9];
    const float* b3   = (const float*)d_in[10];
    float* out = (float*)d_out;

    const int TB = 256;
    const int warpGrid = (NN * 32 + TB - 1) / TB;

    // CSR build (dst layer-invariant)
    k_init<<<(NN + TB - 1) / TB, TB>>>(ei);
    k_convhist<<<(EE + TB - 1) / TB, TB>>>(ei);
    int nb = (NN + 1023) / 1024;
    k_scan1<<<nb, 1024>>>();
    k_scan2<<<1, 128>>>(nb);
    k_scan3<<<(NN + TB - 1) / TB, TB>>>();
    k_scatter<<<(EE + NN + TB - 1) / TB, TB>>>();

    // Layer 1: 128 -> 8x8
    k_gemm<128, 64, 64, 16><<<(NN + 63) / 64, TB>>>(x, W1, 0);
    k_att8<<<warpGrid, TB>>>(att1);
    k_agg8<<<warpGrid, TB>>>(b1, 1);

    // Layer 2: 64 -> 8x8
    k_gemm<64, 64, 64, 16><<<(NN + 63) / 64, TB>>>(nullptr, W2, 1);
    k_att8<<<warpGrid, TB>>>(att2);
    k_agg8<<<warpGrid, TB>>>(b2, 1);

    // Layer 3: 64 -> 1x32
    k_gemm<64, 32, 128, 8><<<(NN + 127) / 128, TB>>>(nullptr, W3, 1);
    k_att32<<<warpGrid, TB>>>(att3);
    k_agg32<<<warpGrid, TB>>>(b3, out);
}

// round 4
// speedup vs baseline: 1.3848x; 1.0728x over previous
#include <cuda_runtime.h>

#define NN 100000
#define EE 1600000
#define NB 98  // (NN + 1023) / 1024

// ---------------- scratch (static device globals; no allocation) ----------------
__device__ int   g_is64;
__device__ int   g_src[EE];
__device__ int   g_dstE[EE];
__device__ int   g_deg[NN];
__device__ int   g_rowptr[NN + 1];
__device__ int   g_cursor[NN];
__device__ int   g_bsum[128];
__device__ int   g_col[EE + NN];
__device__ float g_h[NN * 64];
__device__ float g_act[NN * 64];
__device__ float g_adst[NN * 8];
__device__ float g_asrc[NN * 8];

// ---------------- init: deg=1 (self-loop) + dtype detect ----------------
__global__ void k_init(const void* ei) {
    int i = blockIdx.x * blockDim.x + threadIdx.x;
    if (i < NN) g_deg[i] = 1;
    if (i == 0) {
        const long long* p = (const long long*)ei;
        int ok = 1;
        for (int k = 0; k < 8; k++) {
            long long v = p[k];
            if (v < 0 || v >= NN) ok = 0;
        }
        g_is64 = ok;
    }
}

// ---------------- convert + histogram fused ----------------
__global__ void k_convhist(const void* ei) {
    int e = blockIdx.x * blockDim.x + threadIdx.x;
    if (e >= EE) return;
    int s, d;
    if (g_is64) {
        const long long* p = (const long long*)ei;
        s = (int)p[e];
        d = (int)p[EE + e];
    } else {
        const int* p = (const int*)ei;
        s = p[e];
        d = p[EE + e];
    }
    g_src[e] = s;
    g_dstE[e] = d;
    if (s != d) atomicAdd(&g_deg[d], 1);  // original self-loops dropped (exp(-1e9-amax)==0)
}

// ---------------- scan ----------------
__global__ void k_scan1() {
    __shared__ int sh[1024];
    int tid = threadIdx.x;
    int i = blockIdx.x * 1024 + tid;
    int v = (i < NN) ? g_deg[i] : 0;
    sh[tid] = v;
    __syncthreads();
    for (int o = 1; o < 1024; o <<= 1) {
        int t = (tid >= o) ? sh[tid - o] : 0;
        __syncthreads();
        sh[tid] += t;
        __syncthreads();
    }
    if (i < NN) g_rowptr[i] = sh[tid] - v;
    if (tid == 1023) g_bsum[blockIdx.x] = sh[1023];
}

// scan of block sums done redundantly per block (NB=98 entries, cheap) + apply
__global__ void k_scan23() {
    __shared__ int sh[128];
    int tid = threadIdx.x;
    int i = blockIdx.x * 256 + tid;
    if (tid < 128) sh[tid] = (tid < NB) ? g_bsum[tid] : 0;
    __syncthreads();
    for (int o = 1; o < 128; o <<= 1) {
        int t = (tid >= o && tid < 128) ? sh[tid - o] : 0;
        __syncthreads();
        if (tid < 128) sh[tid] += t;
        __syncthreads();
    }
    if (i < NN) {
        int blk = i >> 10;
        int exc = blk ? sh[blk - 1] : 0;
        int r = g_rowptr[i] + exc;
        g_rowptr[i] = r;
        g_cursor[i] = r;
    }
    if (blockIdx.x == 0 && tid == 0) g_rowptr[NN] = sh[127];
}

__global__ void k_scatter() {
    int e = blockIdx.x * blockDim.x + threadIdx.x;
    if (e >= EE + NN) return;
    if (e < EE) {
        int s = g_src[e], d = g_dstE[e];
        if (s != d) {
            int p = atomicAdd(&g_cursor[d], 1);
            g_col[p] = s;
        }
    } else {
        int n = e - EE;
        int p = atomicAdd(&g_cursor[n], 1);
        g_col[p] = n;
    }
}

// ---------------- tiled FFMA GEMM + fused attention-dot epilogue ----------------
// C[N,NOUT] = A[N,K] @ W[K,NOUT]; then per row: adst/asrc head dots vs att.
template <int K, int NOUT, int MROWS, int TX, int HEADS>
__global__ __launch_bounds__(256) void k_gemm(const float* __restrict__ A,
                                              const float* __restrict__ W,
                                              const float* __restrict__ att,
                                              int use_g_act) {
    __shared__ float Ws[K * NOUT];
    __shared__ float As[MROWS][36];
    const float* Ap = use_g_act ? (const float*)g_act : A;

    int tid = threadIdx.x;
    int row0 = blockIdx.x * MROWS;

    for (int i = tid; i < K * NOUT / 4; i += 256)
        ((float4*)Ws)[i] = ((const float4*)W)[i];

    int tx = tid % TX, ty = tid / TX;
    int r0 = ty * 4, c0 = tx * 4;
    float acc[4][4];
#pragma unroll
    for (int i = 0; i < 4; i++)
#pragma unroll
        for (int j = 0; j < 4; j++) acc[i][j] = 0.f;

    for (int kb = 0; kb < K; kb += 32) {
        __syncthreads();
        for (int f = tid; f < MROWS * 8; f += 256) {
            int r = f >> 3, c4 = f & 7;
            float4 v = make_float4(0.f, 0.f, 0.f, 0.f);
            if (row0 + r < NN)
                v = *(const float4*)&Ap[(row0 + r) * K + kb + c4 * 4];
            *(float4*)&As[r][c4 * 4] = v;
        }
        __syncthreads();
#pragma unroll
        for (int kk = 0; kk < 32; kk++) {
            float a0 = As[r0 + 0][kk];
            float a1 = As[r0 + 1][kk];
            float a2 = As[r0 + 2][kk];
            float a3 = As[r0 + 3][kk];
            float4 b = *(float4*)&Ws[(kb + kk) * NOUT + c0];
            acc[0][0] += a0 * b.x; acc[0][1] += a0 * b.y; acc[0][2] += a0 * b.z; acc[0][3] += a0 * b.w;
            acc[1][0] += a1 * b.x; acc[1][1] += a1 * b.y; acc[1][2] += a1 * b.z; acc[1][3] += a1 * b.w;
            acc[2][0] += a2 * b.x; acc[2][1] += a2 * b.y; acc[2][2] += a2 * b.z; acc[2][3] += a2 * b.w;
            acc[3][0] += a3 * b.x; acc[3][1] += a3 * b.y; acc[3][2] += a3 * b.z; acc[3][3] += a3 * b.w;
        }
    }
    // store C
#pragma unroll
    for (int i = 0; i < 4; i++) {
        int r = row0 + r0 + i;
        if (r < NN)
            *(float4*)&g_h[r * NOUT + c0] =
                make_float4(acc[i][0], acc[i][1], acc[i][2], acc[i][3]);
    }

    // ---- fused attention dots: adst[r,h] = sum_c h*att_d, asrc analog ----
    constexpr int CPH = NOUT / HEADS;  // cols per head
    constexpr int TPH = CPH / 4;       // partials per head
    float wd[4], wsrc[4];
#pragma unroll
    for (int j = 0; j < 4; j++) {
        int col = c0 + j;
        int h = col / CPH, c = col % CPH;
        wd[j]   = att[h * (2 * CPH) + c];
        wsrc[j] = att[h * (2 * CPH) + CPH + c];
    }
    __syncthreads();  // smem tiles now dead; reuse As (dst partials) + Ws (src partials)
#pragma unroll
    for (int i = 0; i < 4; i++) {
        float pd = acc[i][0] * wd[0] + acc[i][1] * wd[1] + acc[i][2] * wd[2] + acc[i][3] * wd[3];
        float ps = acc[i][0] * wsrc[0] + acc[i][1] * wsrc[1] + acc[i][2] * wsrc[2] + acc[i][3] * wsrc[3];
        As[r0 + i][tx] = pd;
        Ws[(r0 + i) * TX + tx] = ps;
    }
    __syncthreads();
    for (int idx = tid; idx < MROWS * HEADS; idx += 256) {
        int r = idx / HEADS, h = idx % HEADS;
        float sd = 0.f, ss = 0.f;
#pragma unroll
        for (int q = 0; q < TPH; q++) {
            sd += As[r][h * TPH + q];
            ss += Ws[r * TX + h * TPH + q];
        }
        int row = row0 + r;
        if (row < NN) {
            g_adst[row * HEADS + h] = sd;
            g_asrc[row * HEADS + h] = ss;
        }
    }
}

// ---------------- aggregate H=8: warp per node, smem-staged weights ----------------
__global__ __launch_bounds__(256) void k_agg8(const float* __restrict__ bias, int do_elu) {
    __shared__ float sw[8][32];
    int t = blockIdx.x * blockDim.x + threadIdx.x;
    int n = t >> 5, lane = t & 31;
    if (n >= NN) return;
    const unsigned full = 0xffffffffu;
    int wb = (threadIdx.x >> 5);
    int start = g_rowptr[n], end = g_rowptr[n + 1];
    int hc = lane & 7;
    int hB = lane >> 2;

    float adst_h = g_adst[n * 8 + hc];
    float2 acc = make_float2(0.f, 0.f);
    float dsum = 0.f;

    for (int base = start; base < end; base += 4) {
        int e = base + (lane >> 3);
        float ex = 0.f;
        int scol = 0;
        if (e < end) {
            scol = g_col[e];
            float a = adst_h + g_asrc[scol * 8 + hc];
            a = a > 0.f ? a : 0.2f * a;
            ex = __expf(a);
        }
        sw[wb][lane] = ex;
        __syncwarp();
#pragma unroll
        for (int j = 0; j < 4; j++) {
            if (base + j >= end) break;
            int s = __shfl_sync(full, scol, j * 8);
            float w = sw[wb][j * 8 + hB];
            float2 hv = *(const float2*)&g_h[s * 64 + lane * 2];
            acc.x += hv.x * w;
            acc.y += hv.y * w;
            dsum += w;
        }
        __syncwarp();
    }
    float inv = 1.f / dsum;
    float o0 = acc.x * inv + bias[lane * 2];
    float o1 = acc.y * inv + bias[lane * 2 + 1];
    if (do_elu) {
        o0 = o0 > 0.f ? o0 : expm1f(o0);
        o1 = o1 > 0.f ? o1 : expm1f(o1);
    }
    *(float2*)&g_act[n * 64 + lane * 2] = make_float2(o0, o1);
}

// ---------------- aggregate H=1: warp per node, paired-edge float2 gather ----------------
__global__ __launch_bounds__(256) void k_agg32(const float* __restrict__ bias,
                                               float* __restrict__ outp) {
    int t = blockIdx.x * blockDim.x + threadIdx.x;
    int n = t >> 5, lane = t & 31;
    if (n >= NN) return;
    const unsigned full = 0xffffffffu;
    int start = g_rowptr[n], end = g_rowptr[n + 1];
    int half = lane >> 4;
    int c2 = (lane & 15) * 2;

    float adst = g_adst[n];
    float2 acc = make_float2(0.f, 0.f);
    float dsum = 0.f;

    for (int base = start; base < end; base += 32) {
        int e = base + lane;
        float ex = 0.f;
        int scol = 0;
        if (e < end) {
            scol = g_col[e];
            float a = adst + g_asrc[scol];
            a = a > 0.f ? a : 0.2f * a;
            ex = __expf(a);
        }
        int cnt = min(32, end - base);
#pragma unroll 4
        for (int j2 = 0; j2 * 2 < cnt; j2++) {
            int j = j2 * 2 + half;
            int s = __shfl_sync(full, scol, j);
            float w = __shfl_sync(full, ex, j);
            if (j < cnt) {
                float2 hv = *(const float2*)&g_h[s * 32 + c2];
                acc.x += hv.x * w;
                acc.y += hv.y * w;
                dsum += w;
            }
        }
    }
    acc.x += __shfl_xor_sync(full, acc.x, 16);
    acc.y += __shfl_xor_sync(full, acc.y, 16);
    dsum += __shfl_xor_sync(full, dsum, 16);
    if (lane < 16) {
        float inv = 1.f / dsum;
        outp[n * 32 + c2] = acc.x * inv + bias[c2];
        outp[n * 32 + c2 + 1] = acc.y * inv + bias[c2 + 1];
    }
}

// ---------------- launch ----------------
extern "C" void kernel_launch(void* const* d_in, const int* in_sizes, int n_in,
                              void* d_out, int out_size) {
    const float* x    = (const float*)d_in[0];
    const void*  ei   = d_in[1];
    const float* W1   = (const float*)d_in[2];
    const float* att1 = (const float*)d_in[3];
    const float* b1   = (const float*)d_in[4];
    const float* W2   = (const float*)d_in[5];
    const float* att2 = (const float*)d_in[6];
    const float* b2   = (const float*)d_in[7];
    const float* W3   = (const float*)d_in[8];
    const float* att3 = (const float*)d_in[9];
    const float* b3   = (const float*)d_in[10];
    float* out = (float*)d_out;

    const int TB = 256;
    const int warpGrid = (NN * 32 + TB - 1) / TB;

    // CSR build (dst layer-invariant)
    k_init<<<(NN + TB - 1) / TB, TB>>>(ei);
    k_convhist<<<(EE + TB - 1) / TB, TB>>>(ei);
    k_scan1<<<NB, 1024>>>();
    k_scan23<<<(NN + 255) / 256, 256>>>();
    k_scatter<<<(EE + NN + TB - 1) / TB, TB>>>();

    // Layer 1: 128 -> 8x8
    k_gemm<128, 64, 64, 16, 8><<<(NN + 63) / 64, TB>>>(x, W1, att1, 0);
    k_agg8<<<warpGrid, TB>>>(b1, 1);

    // Layer 2: 64 -> 8x8
    k_gemm<64, 64, 64, 16, 8><<<(NN + 63) / 64, TB>>>(nullptr, W2, att2, 1);
    k_agg8<<<warpGrid, TB>>>(b2, 1);

    // Layer 3: 64 -> 1x32
    k_gemm<64, 32, 128, 8, 1><<<(NN + 127) / 128, TB>>>(nullptr, W3, att3, 1);
    k_agg32<<<warpGrid, TB>>>(b3, out);
}

// round 5
// speedup vs baseline: 1.4117x; 1.0195x over previous
#include <cuda_runtime.h>
#include <cuda_fp16.h>

#define NN 100000
#define EE 1600000
#define NB 98  // (NN + 1023) / 1024

// ---------------- scratch (static device globals; no allocation) ----------------
__device__ int    g_is64;
__device__ int    g_src[EE];
__device__ int    g_dstE[EE];
__device__ int    g_deg[NN];
__device__ int    g_rowptr[NN + 1];
__device__ int    g_cursor[NN];
__device__ int    g_bsum[128];
__device__ int    g_col[EE + NN];
__device__ __half g_h16[NN * 64];
__device__ float  g_act[NN * 64];
__device__ float  g_adst[NN * 8];
__device__ float  g_asrc[NN * 8];

// ---------------- init: deg=1 (self-loop) + dtype detect ----------------
__global__ void k_init(const void* ei) {
    int i = blockIdx.x * blockDim.x + threadIdx.x;
    if (i < NN) g_deg[i] = 1;
    if (i == 0) {
        const long long* p = (const long long*)ei;
        int ok = 1;
        for (int k = 0; k < 8; k++) {
            long long v = p[k];
            if (v < 0 || v >= NN) ok = 0;
        }
        g_is64 = ok;
    }
}

// ---------------- convert + histogram fused ----------------
__global__ void k_convhist(const void* ei) {
    int e = blockIdx.x * blockDim.x + threadIdx.x;
    if (e >= EE) return;
    int s, d;
    if (g_is64) {
        const long long* p = (const long long*)ei;
        s = (int)p[e];
        d = (int)p[EE + e];
    } else {
        const int* p = (const int*)ei;
        s = p[e];
        d = p[EE + e];
    }
    g_src[e] = s;
    g_dstE[e] = d;
    if (s != d) atomicAdd(&g_deg[d], 1);  // original self-loops dropped (exp(-1e9-amax)==0)
}

// ---------------- scan ----------------
__global__ void k_scan1() {
    __shared__ int sh[1024];
    int tid = threadIdx.x;
    int i = blockIdx.x * 1024 + tid;
    int v = (i < NN) ? g_deg[i] : 0;
    sh[tid] = v;
    __syncthreads();
    for (int o = 1; o < 1024; o <<= 1) {
        int t = (tid >= o) ? sh[tid - o] : 0;
        __syncthreads();
        sh[tid] += t;
        __syncthreads();
    }
    if (i < NN) g_rowptr[i] = sh[tid] - v;
    if (tid == 1023) g_bsum[blockIdx.x] = sh[1023];
}

__global__ void k_scan23() {
    __shared__ int sh[128];
    int tid = threadIdx.x;
    int i = blockIdx.x * 256 + tid;
    if (tid < 128) sh[tid] = (tid < NB) ? g_bsum[tid] : 0;
    __syncthreads();
    for (int o = 1; o < 128; o <<= 1) {
        int t = (tid >= o && tid < 128) ? sh[tid - o] : 0;
        __syncthreads();
        if (tid < 128) sh[tid] += t;
        __syncthreads();
    }
    if (i < NN) {
        int blk = i >> 10;
        int exc = blk ? sh[blk - 1] : 0;
        int r = g_rowptr[i] + exc;
        g_rowptr[i] = r;
        g_cursor[i] = r;
    }
    if (blockIdx.x == 0 && tid == 0) g_rowptr[NN] = sh[127];
}

__global__ void k_scatter() {
    int e = blockIdx.x * blockDim.x + threadIdx.x;
    if (e >= EE + NN) return;
    if (e < EE) {
        int s = g_src[e], d = g_dstE[e];
        if (s != d) {
            int p = atomicAdd(&g_cursor[d], 1);
            g_col[p] = s;
        }
    } else {
        int n = e - EE;
        int p = atomicAdd(&g_cursor[n], 1);
        g_col[p] = n;
    }
}

// ---------------- tiled FFMA GEMM + fused attention-dot epilogue ----------------
// C[N,NOUT] = A[N,K] @ W[K,NOUT]; h stored fp16; adst/asrc from fp32 accumulators.
template <int K, int NOUT, int MROWS, int TX, int HEADS>
__global__ __launch_bounds__(256) void k_gemm(const float* __restrict__ A,
                                              const float* __restrict__ W,
                                              const float* __restrict__ att,
                                              int use_g_act) {
    __shared__ float Ws[K * NOUT];
    __shared__ float As[MROWS][36];
    const float* Ap = use_g_act ? (const float*)g_act : A;

    int tid = threadIdx.x;
    int row0 = blockIdx.x * MROWS;

    for (int i = tid; i < K * NOUT / 4; i += 256)
        ((float4*)Ws)[i] = ((const float4*)W)[i];

    int tx = tid % TX, ty = tid / TX;
    int r0 = ty * 4, c0 = tx * 4;
    float acc[4][4];
#pragma unroll
    for (int i = 0; i < 4; i++)
#pragma unroll
        for (int j = 0; j < 4; j++) acc[i][j] = 0.f;

    for (int kb = 0; kb < K; kb += 32) {
        __syncthreads();
        for (int f = tid; f < MROWS * 8; f += 256) {
            int r = f >> 3, c4 = f & 7;
            float4 v = make_float4(0.f, 0.f, 0.f, 0.f);
            if (row0 + r < NN)
                v = *(const float4*)&Ap[(row0 + r) * K + kb + c4 * 4];
            *(float4*)&As[r][c4 * 4] = v;
        }
        __syncthreads();
#pragma unroll
        for (int kk = 0; kk < 32; kk++) {
            float a0 = As[r0 + 0][kk];
            float a1 = As[r0 + 1][kk];
            float a2 = As[r0 + 2][kk];
            float a3 = As[r0 + 3][kk];
            float4 b = *(float4*)&Ws[(kb + kk) * NOUT + c0];
            acc[0][0] += a0 * b.x; acc[0][1] += a0 * b.y; acc[0][2] += a0 * b.z; acc[0][3] += a0 * b.w;
            acc[1][0] += a1 * b.x; acc[1][1] += a1 * b.y; acc[1][2] += a1 * b.z; acc[1][3] += a1 * b.w;
            acc[2][0] += a2 * b.x; acc[2][1] += a2 * b.y; acc[2][2] += a2 * b.z; acc[2][3] += a2 * b.w;
            acc[3][0] += a3 * b.x; acc[3][1] += a3 * b.y; acc[3][2] += a3 * b.z; acc[3][3] += a3 * b.w;
        }
    }
    // store h as fp16 (4 halves = 8B per thread-row)
#pragma unroll
    for (int i = 0; i < 4; i++) {
        int r = row0 + r0 + i;
        if (r < NN) {
            __half2 lo = __floats2half2_rn(acc[i][0], acc[i][1]);
            __half2 hi = __floats2half2_rn(acc[i][2], acc[i][3]);
            __half2* dst = (__half2*)&g_h16[r * NOUT + c0];
            dst[0] = lo;
            dst[1] = hi;
        }
    }

    // ---- fused attention dots ----
    constexpr int CPH = NOUT / HEADS;
    constexpr int TPH = CPH / 4;
    float wd[4], wsrc[4];
#pragma unroll
    for (int j = 0; j < 4; j++) {
        int col = c0 + j;
        int h = col / CPH, c = col % CPH;
        wd[j]   = att[h * (2 * CPH) + c];
        wsrc[j] = att[h * (2 * CPH) + CPH + c];
    }
    __syncthreads();  // smem tiles dead; reuse As (dst partials) + Ws (src partials)
#pragma unroll
    for (int i = 0; i < 4; i++) {
        float pd = acc[i][0] * wd[0] + acc[i][1] * wd[1] + acc[i][2] * wd[2] + acc[i][3] * wd[3];
        float ps = acc[i][0] * wsrc[0] + acc[i][1] * wsrc[1] + acc[i][2] * wsrc[2] + acc[i][3] * wsrc[3];
        As[r0 + i][tx] = pd;
        Ws[(r0 + i) * TX + tx] = ps;
    }
    __syncthreads();
    for (int idx = tid; idx < MROWS * HEADS; idx += 256) {
        int r = idx / HEADS, h = idx % HEADS;
        float sd = 0.f, ss = 0.f;
#pragma unroll
        for (int q = 0; q < TPH; q++) {
            sd += As[r][h * TPH + q];
            ss += Ws[r * TX + h * TPH + q];
        }
        int row = row0 + r;
        if (row < NN) {
            g_adst[row * HEADS + h] = sd;
            g_asrc[row * HEADS + h] = ss;
        }
    }
}

// ---------------- aggregate H=8: warp per node, fp16 gather ----------------
__global__ __launch_bounds__(256) void k_agg8(const float* __restrict__ bias, int do_elu) {
    __shared__ float sw[8][32];
    int t = blockIdx.x * blockDim.x + threadIdx.x;
    int n = t >> 5, lane = t & 31;
    if (n >= NN) return;
    const unsigned full = 0xffffffffu;
    int wb = (threadIdx.x >> 5);
    int start = g_rowptr[n], end = g_rowptr[n + 1];
    int hc = lane & 7;
    int hB = lane >> 2;

    float adst_h = g_adst[n * 8 + hc];
    float2 acc = make_float2(0.f, 0.f);
    float dsum = 0.f;

    for (int base = start; base < end; base += 4) {
        int e = base + (lane >> 3);
        float ex = 0.f;
        int scol = 0;
        if (e < end) {
            scol = g_col[e];
            float a = adst_h + g_asrc[scol * 8 + hc];
            a = a > 0.f ? a : 0.2f * a;
            ex = __expf(a);
        }
        sw[wb][lane] = ex;
        __syncwarp();
#pragma unroll
        for (int j = 0; j < 4; j++) {
            if (base + j >= end) break;
            int s = __shfl_sync(full, scol, j * 8);
            float w = sw[wb][j * 8 + hB];
            float2 hv = __half22float2(*(const __half2*)&g_h16[s * 64 + lane * 2]);
            acc.x += hv.x * w;
            acc.y += hv.y * w;
            dsum += w;
        }
        __syncwarp();
    }
    float inv = 1.f / dsum;
    float o0 = acc.x * inv + bias[lane * 2];
    float o1 = acc.y * inv + bias[lane * 2 + 1];
    if (do_elu) {
        o0 = o0 > 0.f ? o0 : expm1f(o0);
        o1 = o1 > 0.f ? o1 : expm1f(o1);
    }
    *(float2*)&g_act[n * 64 + lane * 2] = make_float2(o0, o1);
}

// ---------------- aggregate H=1: warp per node, paired-edge fp16 gather ----------------
__global__ __launch_bounds__(256) void k_agg32(const float* __restrict__ bias,
                                               float* __restrict__ outp) {
    int t = blockIdx.x * blockDim.x + threadIdx.x;
    int n = t >> 5, lane = t & 31;
    if (n >= NN) return;
    const unsigned full = 0xffffffffu;
    int start = g_rowptr[n], end = g_rowptr[n + 1];
    int half = lane >> 4;
    int c2 = (lane & 15) * 2;

    float adst = g_adst[n];
    float2 acc = make_float2(0.f, 0.f);
    float dsum = 0.f;

    for (int base = start; base < end; base += 32) {
        int e = base + lane;
        float ex = 0.f;
        int scol = 0;
        if (e < end) {
            scol = g_col[e];
            float a = adst + g_asrc[scol];
            a = a > 0.f ? a : 0.2f * a;
            ex = __expf(a);
        }
        int cnt = min(32, end - base);
#pragma unroll 4
        for (int j2 = 0; j2 * 2 < cnt; j2++) {
            int j = j2 * 2 + half;
            int s = __shfl_sync(full, scol, j);
            float w = __shfl_sync(full, ex, j);
            if (j < cnt) {
                float2 hv = __half22float2(*(const __half2*)&g_h16[s * 32 + c2]);
                acc.x += hv.x * w;
                acc.y += hv.y * w;
                dsum += w;
            }
        }
    }
    acc.x += __shfl_xor_sync(full, acc.x, 16);
    acc.y += __shfl_xor_sync(full, acc.y, 16);
    dsum += __shfl_xor_sync(full, dsum, 16);
    if (lane < 16) {
        float inv = 1.f / dsum;
        outp[n * 32 + c2] = acc.x * inv + bias[c2];
        outp[n * 32 + c2 + 1] = acc.y * inv + bias[c2 + 1];
    }
}

// ---------------- launch ----------------
extern "C" void kernel_launch(void* const* d_in, const int* in_sizes, int n_in,
                              void* d_out, int out_size) {
    const float* x    = (const float*)d_in[0];
    const void*  ei   = d_in[1];
    const float* W1   = (const float*)d_in[2];
    const float* att1 = (const float*)d_in[3];
    const float* b1   = (const float*)d_in[4];
    const float* W2   = (const float*)d_in[5];
    const float* att2 = (const float*)d_in[6];
    const float* b2   = (const float*)d_in[7];
    const float* W3   = (const float*)d_in[8];
    const float* att3 = (const float*)d_in[9];
    const float* b3   = (const float*)d_in[10];
    float* out = (float*)d_out;

    const int TB = 256;
    const int warpGrid = (NN * 32 + TB - 1) / TB;

    // CSR build (dst layer-invariant)
    k_init<<<(NN + TB - 1) / TB, TB>>>(ei);
    k_convhist<<<(EE + TB - 1) / TB, TB>>>(ei);
    k_scan1<<<NB, 1024>>>();
    k_scan23<<<(NN + 255) / 256, 256>>>();
    k_scatter<<<(EE + NN + TB - 1) / TB, TB>>>();

    // Layer 1: 128 -> 8x8
    k_gemm<128, 64, 64, 16, 8><<<(NN + 63) / 64, TB>>>(x, W1, att1, 0);
    k_agg8<<<warpGrid, TB>>>(b1, 1);

    // Layer 2: 64 -> 8x8
    k_gemm<64, 64, 64, 16, 8><<<(NN + 63) / 64, TB>>>(nullptr, W2, att2, 1);
    k_agg8<<<warpGrid, TB>>>(b2, 1);

    // Layer 3: 64 -> 1x32
    k_gemm<64, 32, 128, 8, 1><<<(NN + 127) / 128, TB>>>(nullptr, W3, att3, 1);
    k_agg32<<<warpGrid, TB>>>(b3, out);
}